// round 4
// baseline (speedup 1.0000x reference)
#include <cuda_runtime.h>
#include <cuda_fp16.h>
#include <mma.h>
#include <cstdint>

using namespace nvcuda;

// Problem dims (fixed by setup_inputs)
constexpr int U = 128, I = 256, J = 512, C = 128, E = 128;

// ---------------- scratch (device globals; no allocation allowed) ----------
__device__ float  g_st[U * I];             // s_t
__device__ float  g_skb[U * J];            // s_k + b_dense
__device__ float  g_upart[U * C];          // user @ W1 + b_mlp
__device__ float  g_maskf[U * J];          // canonical mask as float 0/1
__device__ int    g_mask_mode;             // 0=byte, 1=int32, 2=float32
__device__ __half g_inter_h[U * J * C];    // interacted, fp16
__device__ __half g_W2h[C * C];            // W_mlp[E:], fp16
__device__ float  g_Zf[U * J * C];         // Z = interacted @ W2, fp32
__device__ __half g_Zh[U * J * C];         // Z fp16
__device__ __half g_attn_h[U * I * J];     // attn fp16 (GEMM A operand)

// ---------------- mask dtype sniffing ---------------------------------------
// Reads ONLY the first 16384 32-bit words (64 KB) — safe whether the buffer is
// U*J bytes (bool) or U*J words (int32/float32).
//   int32 layout : every word is 0 or 1
//   float32      : every word is 0 or 0x3F800000 (1.0f)
//   packed bytes : words mix bytes {0,1} -> neither of the above
__global__ void detect_mask_kernel(const unsigned* __restrict__ m)
{
    __shared__ int s_a, s_b;
    if (threadIdx.x == 0) { s_a = 0; s_b = 0; }
    __syncthreads();
    int a = 0, b = 0;
    for (int i = threadIdx.x; i < (U * J) / 4; i += blockDim.x) {
        unsigned w = m[i];
        a |= (w != 0u && w != 1u);
        b |= (w != 0u && w != 0x3F800000u);
    }
    if (a) atomicOr(&s_a, 1);
    if (b) atomicOr(&s_b, 1);
    __syncthreads();
    if (threadIdx.x == 0) {
        int mode;
        if (!s_a)      mode = 1;   // all {0,1}            -> int32
        else if (!s_b) mode = 2;   // all {0,1.0f}         -> float32
        else           mode = 0;   // mixed byte patterns  -> bool bytes
        g_mask_mode = mode;
    }
}

__global__ __launch_bounds__(256) void maskconv_kernel(const void* __restrict__ m)
{
    int i = blockIdx.x * 256 + threadIdx.x;
    int mode = g_mask_mode;
    int v;
    if (mode == 1)      v = ((const int*)m)[i] != 0;
    else if (mode == 2) v = ((const float*)m)[i] != 0.f;
    else                v = ((const unsigned char*)m)[i] != 0;
    g_maskf[i] = (float)v;
}

// ---------------- warp-per-row dot: s = row . w (+bias); optional fp16 copy
__global__ __launch_bounds__(256) void row_dot_kernel(
    const float* __restrict__ rows, const float* __restrict__ w,
    const float* __restrict__ bias_ptr, float* __restrict__ out,
    __half* __restrict__ out_h, int nrows)
{
    int warp = (blockIdx.x * blockDim.x + threadIdx.x) >> 5;
    if (warp >= nrows) return;
    int lane = threadIdx.x & 31;
    float4 v  = *(const float4*)(rows + (size_t)warp * 128 + lane * 4);
    float4 wv = __ldg((const float4*)w + lane);
    if (out_h) {
        ((__half2*)out_h)[(size_t)warp * 64 + lane * 2]     = __floats2half2_rn(v.x, v.y);
        ((__half2*)out_h)[(size_t)warp * 64 + lane * 2 + 1] = __floats2half2_rn(v.z, v.w);
    }
    float d = v.x * wv.x + v.y * wv.y + v.z * wv.z + v.w * wv.w;
    #pragma unroll
    for (int off = 16; off; off >>= 1) d += __shfl_xor_sync(0xffffffffu, d, off);
    if (lane == 0) out[warp] = d + (bias_ptr ? bias_ptr[0] : 0.f);
}

// ---------------- u_part = user @ W_mlp[:E] + b_mlp -------------------------
__global__ void upart_kernel(const float* __restrict__ user,
                             const float* __restrict__ Wmlp,
                             const float* __restrict__ bmlp)
{
    int u = blockIdx.x, c = threadIdx.x;
    float acc = bmlp[c];
    #pragma unroll 8
    for (int e = 0; e < E; e++)
        acc += user[u * E + e] * __ldg(Wmlp + e * C + c);
    g_upart[u * C + c] = acc;
}

// ---------------- W2 -> fp16 -------------------------------------------------
__global__ void w2conv_kernel(const float* __restrict__ Wmlp)
{
    int i = blockIdx.x * blockDim.x + threadIdx.x;
    if (i < C * C) g_W2h[i] = __float2half(Wmlp[E * C + i]);
}

// ---------------- attention: attn = softmax_j( tanh(st+skb) masked ) -------
// block = 256 thr (8 warps). grid = U*4 (each block: one u, 64 i-rows).
// lane owns j = q*64 + 2*lane + {0,1}, q=0..7 (16 j per lane, warp covers 512).
__global__ __launch_bounds__(256) void attn_kernel(
    float* __restrict__ attn_out, __half* __restrict__ attn_h)
{
    const int u  = blockIdx.x >> 2;
    const int ib = (blockIdx.x & 3) * 64;
    const int wid = threadIdx.x >> 5, lane = threadIdx.x & 31;
    const float L2E = 1.4426950408889634f;

    float2 skb2[8], mm2[8];
    #pragma unroll
    for (int q = 0; q < 8; q++) {
        int j = q * 64 + 2 * lane;
        skb2[q] = *(const float2*)(g_skb + u * J + j);
        mm2[q]  = *(const float2*)(g_maskf + u * J + j);
    }

    for (int it = 0; it < 8; it++) {
        int i = ib + it * 8 + wid;
        float st = g_st[u * I + i];
        float fr[16];
        float sum = 0.f;
        #pragma unroll
        for (int q = 0; q < 8; q++) {
            float x0 = st + skb2[q].x, x1 = st + skb2[q].y;
            float t0, t1, e0, e1;
            asm("tanh.approx.f32 %0, %1;" : "=f"(t0) : "f"(x0));
            asm("tanh.approx.f32 %0, %1;" : "=f"(t1) : "f"(x1));
            asm("ex2.approx.f32 %0, %1;"  : "=f"(e0) : "f"(t0 * L2E));
            asm("ex2.approx.f32 %0, %1;"  : "=f"(e1) : "f"(t1 * L2E));
            e0 *= mm2[q].x; e1 *= mm2[q].y;
            fr[2 * q] = e0; fr[2 * q + 1] = e1;
            sum += e0 + e1;
        }
        #pragma unroll
        for (int off = 16; off; off >>= 1)
            sum += __shfl_xor_sync(0xffffffffu, sum, off);
        float inv = __fdividef(1.f, sum);
        int base = (u * I + i) * J;
        #pragma unroll
        for (int q = 0; q < 8; q++) {
            int j = q * 64 + 2 * lane;
            float a0 = fr[2 * q] * inv, a1 = fr[2 * q + 1] * inv;
            *(float2*)(attn_out + base + j)   = make_float2(a0, a1);
            *(__half2*)(attn_h + base + j)    = __floats2half2_rn(a0, a1);
        }
    }
}

// ---------------- GEMM tiles: BM=64, BN=128, BK=64; 8 warps (2x4), 32x32/warp
constexpr int LDA_S = 72;   // half, padded
constexpr int LDB_S = 136;  // half, padded

__device__ __forceinline__ void gemm_tile_mma(
    const __half* As, const __half* Bs, int wm, int wn,
    wmma::fragment<wmma::accumulator, 16, 16, 16, float> acc[2][2])
{
    #pragma unroll
    for (int kk = 0; kk < 64; kk += 16) {
        wmma::fragment<wmma::matrix_a, 16, 16, 16, __half, wmma::row_major> a[2];
        wmma::fragment<wmma::matrix_b, 16, 16, 16, __half, wmma::row_major> b[2];
        wmma::load_matrix_sync(a[0], As + (wm * 32) * LDA_S + kk, LDA_S);
        wmma::load_matrix_sync(a[1], As + (wm * 32 + 16) * LDA_S + kk, LDA_S);
        wmma::load_matrix_sync(b[0], Bs + kk * LDB_S + wn * 32, LDB_S);
        wmma::load_matrix_sync(b[1], Bs + kk * LDB_S + wn * 32 + 16, LDB_S);
        #pragma unroll
        for (int fi = 0; fi < 2; fi++)
            #pragma unroll
            for (int fj = 0; fj < 2; fj++)
                wmma::mma_sync(acc[fi][fj], a[fi], b[fj], acc[fi][fj]);
    }
}

// Z[u] = interacted_h[u] (JxC) @ W2h (CxC), fp32 out to g_Zf
__global__ __launch_bounds__(256) void gemm_z_kernel()
{
    __shared__ __align__(16) __half As[64 * LDA_S];
    __shared__ __align__(16) __half Bs[64 * LDB_S];
    const int u = blockIdx.y, m0 = blockIdx.x * 64;
    const __half* A = g_inter_h + (size_t)u * J * C;
    const __half* B = g_W2h;
    const int tid = threadIdx.x, wid = tid >> 5;
    const int wm = wid >> 2, wn = wid & 3;

    wmma::fragment<wmma::accumulator, 16, 16, 16, float> acc[2][2];
    #pragma unroll
    for (int fi = 0; fi < 2; fi++)
        for (int fj = 0; fj < 2; fj++) wmma::fill_fragment(acc[fi][fj], 0.f);

    for (int k0 = 0; k0 < C; k0 += 64) {
        #pragma unroll
        for (int r = 0; r < 2; r++) {
            int idx = tid + 256 * r, row = idx >> 3, c8 = (idx & 7) * 8;
            *(int4*)(As + row * LDA_S + c8) =
                *(const int4*)(A + (m0 + row) * C + k0 + c8);
        }
        #pragma unroll
        for (int r = 0; r < 4; r++) {
            int idx = tid + 256 * r, row = idx >> 4, c8 = (idx & 15) * 8;
            *(int4*)(Bs + row * LDB_S + c8) =
                *(const int4*)(B + (k0 + row) * C + c8);
        }
        __syncthreads();
        gemm_tile_mma(As, Bs, wm, wn, acc);
        __syncthreads();
    }
    float* Cg = g_Zf + (size_t)u * J * C;
    #pragma unroll
    for (int fi = 0; fi < 2; fi++)
        for (int fj = 0; fj < 2; fj++)
            wmma::store_matrix_sync(
                Cg + (m0 + wm * 32 + fi * 16) * C + wn * 32 + fj * 16,
                acc[fi][fj], C, wmma::mem_row_major);
}

__global__ __launch_bounds__(256) void convz_kernel()
{
    int i = blockIdx.x * 256 + threadIdx.x;   // over float4s
    float4 v = *((const float4*)g_Zf + i);
    ((__half2*)g_Zh)[2 * i]     = __floats2half2_rn(v.x, v.y);
    ((__half2*)g_Zh)[2 * i + 1] = __floats2half2_rn(v.z, v.w);
}

// user_context[u] = relu(upart[u] + attn_h[u] (IxJ) @ Zh[u] (JxC))
__global__ __launch_bounds__(256) void gemm_main_kernel(float* __restrict__ out)
{
    __shared__ __align__(16) char smem_raw[64 * 128 * 4];  // 32 KB union
    __half* As = (__half*)smem_raw;
    __half* Bs = (__half*)(smem_raw + 64 * LDA_S * 2);
    float*  Cs = (float*)smem_raw;

    const int u = blockIdx.y, m0 = blockIdx.x * 64;
    const __half* A = g_attn_h + (size_t)u * I * J;
    const __half* B = g_Zh + (size_t)u * J * C;
    const int tid = threadIdx.x, wid = tid >> 5;
    const int wm = wid >> 2, wn = wid & 3;

    wmma::fragment<wmma::accumulator, 16, 16, 16, float> acc[2][2];
    #pragma unroll
    for (int fi = 0; fi < 2; fi++)
        for (int fj = 0; fj < 2; fj++) wmma::fill_fragment(acc[fi][fj], 0.f);

    for (int k0 = 0; k0 < J; k0 += 64) {
        #pragma unroll
        for (int r = 0; r < 2; r++) {
            int idx = tid + 256 * r, row = idx >> 3, c8 = (idx & 7) * 8;
            *(int4*)(As + row * LDA_S + c8) =
                *(const int4*)(A + (m0 + row) * J + k0 + c8);
        }
        #pragma unroll
        for (int r = 0; r < 4; r++) {
            int idx = tid + 256 * r, row = idx >> 4, c8 = (idx & 15) * 8;
            *(int4*)(Bs + row * LDB_S + c8) =
                *(const int4*)(B + (k0 + row) * C + c8);
        }
        __syncthreads();
        gemm_tile_mma(As, Bs, wm, wn, acc);
        __syncthreads();
    }

    // stage accumulators, then fused epilogue: relu(acc + upart)
    #pragma unroll
    for (int fi = 0; fi < 2; fi++)
        for (int fj = 0; fj < 2; fj++)
            wmma::store_matrix_sync(
                Cs + (wm * 32 + fi * 16) * 128 + wn * 32 + fj * 16,
                acc[fi][fj], 128, wmma::mem_row_major);
    __syncthreads();

    const float4* up4 = (const float4*)(g_upart + u * C);
    float* outbase = out + (size_t)(u * I + m0) * C;
    #pragma unroll
    for (int r = 0; r < 8; r++) {
        int idx = tid + 256 * r;            // 2048 float4s
        int row = idx >> 5, c4 = idx & 31;
        float4 v  = ((const float4*)Cs)[idx];
        float4 up = __ldg(up4 + c4);
        v.x = fmaxf(v.x + up.x, 0.f);
        v.y = fmaxf(v.y + up.y, 0.f);
        v.z = fmaxf(v.z + up.z, 0.f);
        v.w = fmaxf(v.w + up.w, 0.f);
        ((float4*)outbase)[row * 32 + c4] = v;
    }
}

// ---------------- launcher ---------------------------------------------------
extern "C" void kernel_launch(void* const* d_in, const int* in_sizes, int n_in,
                              void* d_out, int out_size)
{
    const float* target = (const float*)d_in[0];  // (U,I,C)
    const float* inter  = (const float*)d_in[1];  // (U,J,C)
    const float* user   = (const float*)d_in[2];  // (U,E)
    const void*  mask   = d_in[3];                // (U,J) dtype sniffed on device
    const float* wdense = (const float*)d_in[4];  // (2C,)
    const float* bdense = (const float*)d_in[5];  // (1,)
    const float* Wmlp   = (const float*)d_in[6];  // (E+C, C)
    const float* bmlp   = (const float*)d_in[7];  // (C,)

    float* out_ctx  = (float*)d_out;                       // (U,I,C)
    float* out_attn = (float*)d_out + (size_t)U * I * C;   // (U,I,J)

    float*  st_p;     cudaGetSymbolAddress((void**)&st_p, g_st);
    float*  skb_p;    cudaGetSymbolAddress((void**)&skb_p, g_skb);
    __half* interh_p; cudaGetSymbolAddress((void**)&interh_p, g_inter_h);
    __half* attnh_p;  cudaGetSymbolAddress((void**)&attnh_p, g_attn_h);

    // mask dtype sniff + canonicalize to float 0/1
    detect_mask_kernel<<<1, 1024>>>((const unsigned*)mask);
    maskconv_kernel<<<(U * J) / 256, 256>>>(mask);

    // s_t = target . w1  (no bias, no fp16 copy)
    row_dot_kernel<<<(U * I) / 8, 256>>>(target, wdense, nullptr,
                                         st_p, nullptr, U * I);
    // s_kb = inter . w2 + b ; also emit fp16 interacted
    row_dot_kernel<<<(U * J) / 8, 256>>>(inter, wdense + C, bdense,
                                         skb_p, interh_p, U * J);
    upart_kernel<<<U, C>>>(user, Wmlp, bmlp);
    w2conv_kernel<<<(C * C) / 256, 256>>>(Wmlp);

    attn_kernel<<<U * 4, 256>>>(out_attn, attnh_p);

    gemm_z_kernel<<<dim3(J / 64, U), 256>>>();
    convz_kernel<<<(U * J * C) / 4 / 256, 256>>>();
    gemm_main_kernel<<<dim3(I / 64, U), 256>>>(out_ctx);
}